// round 9
// baseline (speedup 1.0000x reference)
#include <cuda_runtime.h>
#include <cuda_bf16.h>
#include <cstdint>

#define M_CONST   100
#define GROUPS    25      // M/4 float4 groups per row
#define ROWS_HALF 10
#define ROWS_ITER 20      // rows per block iteration (2 per thread)
#define ACTIVE    (GROUPS * ROWS_HALF)   // 250 active threads

__device__ __forceinline__ float ex2_(float x) {
    float r; asm("ex2.approx.f32 %0, %1;" : "=f"(r) : "f"(x)); return r;
}
__device__ __forceinline__ float rcp_(float x) {
    float r; asm("rcp.approx.f32 %0, %1;" : "=f"(r) : "f"(x)); return r;
}

#define NEG_HALF_LOG2E -0.7213475204444817f  // -0.5*log2(e): exp -> ex2
#define INV_TWO_PI      0.15915494309189535f

struct RowP { float s00, s01, s11, mu0, mu1, ns01q, s01_2; };

__device__ __forceinline__ RowP row_setup(const float2* __restrict__ th2, int n) {
    const float2 e  = th2[(size_t)n * 3 + 0];
    const float2 q0 = th2[(size_t)n * 3 + 1];
    const float2 q1 = th2[(size_t)n * 3 + 2];
    const float d   = q0.x * q1.y - q0.y * q1.x;
    const float r   = rcp_(d);                    // MUFU.RCP
    const float u01 = -0.5f * (q0.y + q1.x);
    const float m0p = q1.y * e.x + u01 * e.y;     // overlap RCP latency
    const float m1p = u01 * e.x + q0.x * e.y;
    const float inv = -0.5f * r;                  // = -1/(2d)
    RowP p;
    p.s00  = q1.y * inv;
    p.s11  = q0.x * inv;
    p.s01  = u01  * inv;
    p.mu0  = m0p * inv;
    p.mu1  = m1p * inv;
    p.ns01q = -(p.s01 * p.s01);
    p.s01_2 = p.s01 + p.s01;
    return p;
}

// basis_sigma is diagonal (reference: vmap(diag)(var)):
//   det  = c00*c11 - s01^2,  quad = (c11 dx^2 - 2 s01 dx dy + c00 dy^2)/det
// Thread t (<250): basis group g = t%25 cached in registers; handles TWO
// independent rows per iteration (r_local and r_local+10) for in-warp ILP.
__global__ __launch_bounds__(256) void ContinuousSoftmax_kernel(
    const float* __restrict__ theta,        // [N,6]
    const float* __restrict__ basis_mu,     // [M,2]
    const float* __restrict__ basis_sigma,  // [M,2,2] diagonal
    float* __restrict__ out,                // [N,M]
    int N)
{
    const int tid = threadIdx.x;
    if (tid >= ACTIVE) return;
    const int r_local = tid / GROUPS;             // 0..9
    const int g       = tid - r_local * GROUPS;   // 0..24

    // ---- one-time: cache this thread's 4 basis entries in registers ----
    const float4* bm = reinterpret_cast<const float4*>(basis_mu) + 2 * g;
    const float4  m01 = bm[0];
    const float4  m23 = bm[1];
    const float4* bs = reinterpret_cast<const float4*>(basis_sigma) + 4 * g;
    const float4  sg0 = bs[0], sg1 = bs[1], sg2 = bs[2], sg3 = bs[3];

    const float nbm0[4] = {-m01.x, -m01.z, -m23.x, -m23.z};
    const float nbm1[4] = {-m01.y, -m01.w, -m23.y, -m23.w};
    const float av[4]   = {sg0.x, sg1.x, sg2.x, sg3.x};   // diag var_x
    const float bv[4]   = {sg0.w, sg1.w, sg2.w, sg3.w};   // diag var_y

    const int stride = gridDim.x * ROWS_ITER;
    const float2* th2 = reinterpret_cast<const float2*>(theta);

    for (int base = blockIdx.x * ROWS_ITER; base < N; base += stride) {
        const int nA = base + r_local;
        const int nB = nA + ROWS_HALF;
        if (nA >= N) break;
        const bool hasB = (nB < N);

        // Two independent setup chains (LDGs + RCPs overlap each other).
        const RowP A = row_setup(th2, nA);
        const RowP B = row_setup(th2, hasB ? nB : nA);

        float resA[4], resB[4];
        #pragma unroll
        for (int k = 0; k < 4; ++k) {
            // --- row A, element k ---
            const float a_c00 = A.s00 + av[k];
            const float a_c11 = A.s11 + bv[k];
            const float a_dx  = A.mu0 + nbm0[k];
            const float a_dy  = A.mu1 + nbm1[k];
            const float a_det = fmaf(a_c00, a_c11, A.ns01q);
            const float a_rs  = rsqrtf(a_det);            // MUFU.RSQ
            // --- row B, element k (independent: fills A's RSQ shadow) ---
            const float b_c00 = B.s00 + av[k];
            const float b_c11 = B.s11 + bv[k];
            const float b_dx  = B.mu0 + nbm0[k];
            const float b_dy  = B.mu1 + nbm1[k];
            const float b_det = fmaf(b_c00, b_c11, B.ns01q);
            const float b_rs  = rsqrtf(b_det);

            const float a_in  = fmaf(a_c11, a_dx, -(A.s01_2 * a_dy));
            const float a_num = fmaf(a_c00 * a_dy, a_dy, a_dx * a_in);
            const float b_in  = fmaf(b_c11, b_dx, -(B.s01_2 * b_dy));
            const float b_num = fmaf(b_c00 * b_dy, b_dy, b_dx * b_in);

            const float a_arg = ((a_num * NEG_HALF_LOG2E) * a_rs) * a_rs;
            const float b_arg = ((b_num * NEG_HALF_LOG2E) * b_rs) * b_rs;
            resA[k] = ex2_(a_arg) * (a_rs * INV_TWO_PI);  // MUFU.EX2
            resB[k] = ex2_(b_arg) * (b_rs * INV_TWO_PI);
        }
        *reinterpret_cast<float4*>(out + (size_t)nA * M_CONST + 4 * g) =
            make_float4(resA[0], resA[1], resA[2], resA[3]);
        if (hasB)
            *reinterpret_cast<float4*>(out + (size_t)nB * M_CONST + 4 * g) =
                make_float4(resB[0], resB[1], resB[2], resB[3]);
    }
}

extern "C" void kernel_launch(void* const* d_in, const int* in_sizes, int n_in,
                              void* d_out, int out_size) {
    const float* theta       = (const float*)d_in[0];
    const float* basis_mu    = (const float*)d_in[1];
    const float* basis_sigma = (const float*)d_in[2];
    float* out = (float*)d_out;

    const int N = in_sizes[0] / 6;

    const int threads = 256;
    const int needed  = (N + ROWS_ITER - 1) / ROWS_ITER;
    int blocks = 1184;              // 148 SMs x 4 CTAs x 2 waves
    if (blocks > needed) blocks = needed;
    ContinuousSoftmax_kernel<<<blocks, threads>>>(theta, basis_mu, basis_sigma,
                                                  out, N);
}